// round 9
// baseline (speedup 1.0000x reference)
#include <cuda_runtime.h>
#include <cuda_bf16.h>
#include <float.h>

// LabelLoss: B=16, K=11, H=W=128, C=7 — single kernel, serial-tail minimized.
//   pooled = 3x3 box-sum (pad 1) of heatmap[b,k]  (÷9 dropped: argmax-invariant)
//   idx    = argmax over flattened HxW (first occurrence)
//   loss[b,k] = sum_c (pred[b, k*7+c, idx/W, idx%W] - gt[b,k,c])^2
//   out[b] = mean_k loss[b,k]   (last CTA, warp 0 only)
//
// One CTA per (b,k): 176 CTAs x 512 threads, all co-resident.
// CTA argmax: each thread smem-atomicMax's a packed u64:
//   hi = monotone ordered-uint(pooled), lo = ~idx  (bigger lo <=> smaller idx
//   => first-occurrence tie-break).

#define BVAL 16
#define KVAL 11
#define NBK  (BVAL * KVAL)          // 176
#define HVAL 128
#define WVAL 128
#define HW   (HVAL * WVAL)
#define CVAL 7
#define NTHREADS 512                // 16 warps; warp w owns rows [8w, 8w+8)

__device__ float        g_labelloss_scratch[NBK];
__device__ unsigned int g_labelloss_count = 0;

__device__ __forceinline__ unsigned int float_to_ordered(float f)
{
    unsigned int u = __float_as_uint(f);
    return (u & 0x80000000u) ? ~u : (u | 0x80000000u);  // monotone, >0 for finite f
}

__global__ __launch_bounds__(NTHREADS)
void labelloss_fused_kernel(const float* __restrict__ pred,
                            const float* __restrict__ gt,
                            const float* __restrict__ heatmap,
                            float* __restrict__ out)
{
    const int bk   = blockIdx.x;            // b*K + k
    const int tid  = threadIdx.x;
    const int lane = tid & 31;
    const int warp = tid >> 5;              // 0..15
    const int x0   = warp * 8;              // row strip start
    const int c0   = lane * 4;              // 4 columns per lane

    __shared__ unsigned long long s_best;
    if (tid == 0) s_best = 0ull;

    const float* __restrict__ hm = heatmap + (size_t)bk * HW;

    // ---- Phase 1: front-batch all loads (rows x0-1 .. x0+8) -> MLP = 10 ----
    float4 v[10];
    #pragma unroll
    for (int i = 0; i < 10; ++i) {
        const int x = x0 - 1 + i;
        if ((unsigned)x < (unsigned)HVAL) {
            v[i] = *reinterpret_cast<const float4*>(hm + x * WVAL + c0);
        } else {
            v[i] = make_float4(0.f, 0.f, 0.f, 0.f);
        }
    }

    // ---- Phase 2: horizontal 3-tap per row (lane shuffles) ----
    float4 rs[10];
    #pragma unroll
    for (int i = 0; i < 10; ++i) {
        float left  = __shfl_up_sync(0xffffffffu, v[i].w, 1);
        float right = __shfl_down_sync(0xffffffffu, v[i].x, 1);
        if (lane == 0)  left  = 0.f;
        if (lane == 31) right = 0.f;
        rs[i].x = left    + v[i].x + v[i].y;
        rs[i].y = v[i].x  + v[i].y + v[i].z;
        rs[i].z = v[i].y  + v[i].z + v[i].w;
        rs[i].w = v[i].z  + v[i].w + right;
    }

    // ---- Phase 3: vertical 3-tap + per-thread argmax ----
    float best = -FLT_MAX;
    int   bidx = 0x7FFFFFFF;
    #pragma unroll
    for (int j = 0; j < 8; ++j) {
        const int x = x0 + j;
        float p0 = rs[j].x + rs[j + 1].x + rs[j + 2].x;
        float p1 = rs[j].y + rs[j + 1].y + rs[j + 2].y;
        float p2 = rs[j].z + rs[j + 1].z + rs[j + 2].z;
        float p3 = rs[j].w + rs[j + 1].w + rs[j + 2].w;
        const int base = x * WVAL + c0;
        if (p0 > best) { best = p0; bidx = base;     }
        if (p1 > best) { best = p1; bidx = base + 1; }
        if (p2 > best) { best = p2; bidx = base + 2; }
        if (p3 > best) { best = p3; bidx = base + 3; }
    }

    // ---- Phase 4: single-shot CTA argmax via smem u64 atomicMax ----
    const unsigned long long packed =
        ((unsigned long long)float_to_ordered(best) << 32) |
        (unsigned long long)(~(unsigned int)bidx);
    __syncthreads();                         // s_best init visible
    atomicMax(&s_best, packed);
    __syncthreads();                         // all contributions in

    // ---- Phase 5: warp 0 finishes: gather, loss, counter, maybe final mean ----
    if (warp == 0) {
        unsigned cnt = 0;
        if (lane == 0) {
            const int idx = (int)(~(unsigned int)(s_best & 0xFFFFFFFFull));
            const float* __restrict__ pk = pred + (size_t)bk * CVAL * HW;
            const float* __restrict__ g  = gt   + (size_t)bk * CVAL;
            float loss = 0.0f;
            #pragma unroll
            for (int c = 0; c < CVAL; ++c) {
                float d = pk[c * HW + idx] - g[c];
                loss = fmaf(d, d, loss);
            }
            g_labelloss_scratch[bk] = loss;
            __threadfence();                              // scratch before count
            cnt = atomicAdd(&g_labelloss_count, 1u);
        }
        cnt = __shfl_sync(0xffffffffu, cnt, 0);

        if (cnt == NBK - 1) {                             // last CTA: final mean
            __threadfence();                              // acquire all scratch
            if (lane < BVAL) {
                float s = 0.0f;
                #pragma unroll
                for (int k = 0; k < KVAL; ++k)            // MLP=11, fixed order
                    s += g_labelloss_scratch[lane * KVAL + k];
                out[lane] = s * (1.0f / (float)KVAL);
            }
            if (lane == 0) g_labelloss_count = 0;         // reset for next replay
        }
    }
}

extern "C" void kernel_launch(void* const* d_in, const int* in_sizes, int n_in,
                              void* d_out, int out_size)
{
    const float* pred    = (const float*)d_in[0];
    const float* gt      = (const float*)d_in[1];
    const float* heatmap = (const float*)d_in[2];
    float* out = (float*)d_out;

    labelloss_fused_kernel<<<NBK, NTHREADS>>>(pred, gt, heatmap, out);
}

// round 10
// speedup vs baseline: 1.0029x; 1.0029x over previous
#include <cuda_runtime.h>
#include <cuda_bf16.h>
#include <float.h>

// LabelLoss: B=16, K=11, H=W=128, C=7 — single fused kernel.
//   pooled = 3x3 box-sum (pad 1) of heatmap[b,k]  (÷9 dropped: argmax-invariant)
//   idx    = argmax over flattened HxW (first occurrence)
//   loss[b,k] = sum_c (pred[b, k*7+c, idx/W, idx%W] - gt[b,k,c])^2
//   out[b] = mean_k loss[b,k]   (last CTA to finish)
//
// One CTA per (b,k): 176 CTAs x 512 threads, all co-resident.
// Pooling: vertical 3-tap first (thread-local), then horizontal 3-tap
// (2 shuffles per OUTPUT row -> 16 shuffles/thread).
// CTA argmax: 5-step warp shfl reduce, then 16 lane-0 smem atomicMax of
// packed u64 (hi = ordered-uint(pooled), lo = ~idx: bigger lo <=> smaller
// idx => first-occurrence tie-break).

#define BVAL 16
#define KVAL 11
#define NBK  (BVAL * KVAL)          // 176
#define HVAL 128
#define WVAL 128
#define HW   (HVAL * WVAL)
#define CVAL 7
#define NTHREADS 512                // 16 warps; warp w owns rows [8w, 8w+8)

__device__ float        g_labelloss_scratch[NBK];
__device__ unsigned int g_labelloss_count = 0;

__device__ __forceinline__ unsigned int float_to_ordered(float f)
{
    unsigned int u = __float_as_uint(f);
    return (u & 0x80000000u) ? ~u : (u | 0x80000000u);  // monotone, >0 finite
}

__global__ __launch_bounds__(NTHREADS)
void labelloss_fused_kernel(const float* __restrict__ pred,
                            const float* __restrict__ gt,
                            const float* __restrict__ heatmap,
                            float* __restrict__ out)
{
    const int bk   = blockIdx.x;            // b*K + k
    const int tid  = threadIdx.x;
    const int lane = tid & 31;
    const int warp = tid >> 5;              // 0..15
    const int x0   = warp * 8;              // row strip start
    const int c0   = lane * 4;              // 4 columns per lane

    __shared__ unsigned long long s_best;
    if (tid == 0) s_best = 0ull;

    const float* __restrict__ hm = heatmap + (size_t)bk * HW;

    // ---- Phase 1: front-batch all loads (rows x0-1 .. x0+8) -> MLP = 10 ----
    float4 v[10];
    #pragma unroll
    for (int i = 0; i < 10; ++i) {
        const int x = x0 - 1 + i;
        if ((unsigned)x < (unsigned)HVAL) {
            v[i] = *reinterpret_cast<const float4*>(hm + x * WVAL + c0);
        } else {
            v[i] = make_float4(0.f, 0.f, 0.f, 0.f);
        }
    }

    // ---- Phase 2: vertical 3-tap FIRST (thread-local, no communication) ----
    float4 cs[8];
    #pragma unroll
    for (int j = 0; j < 8; ++j) {
        cs[j].x = v[j].x + v[j + 1].x + v[j + 2].x;
        cs[j].y = v[j].y + v[j + 1].y + v[j + 2].y;
        cs[j].z = v[j].z + v[j + 1].z + v[j + 2].z;
        cs[j].w = v[j].w + v[j + 1].w + v[j + 2].w;
    }

    // ---- Phase 3: horizontal 3-tap per OUTPUT row (2 shuffles/row) + argmax ----
    float best = -FLT_MAX;
    int   bidx = 0x7FFFFFFF;
    #pragma unroll
    for (int j = 0; j < 8; ++j) {
        float left  = __shfl_up_sync(0xffffffffu, cs[j].w, 1);
        float right = __shfl_down_sync(0xffffffffu, cs[j].x, 1);
        if (lane == 0)  left  = 0.f;        // column -1 pad
        if (lane == 31) right = 0.f;        // column 128 pad
        float p0 = left     + cs[j].x + cs[j].y;
        float p1 = cs[j].x  + cs[j].y + cs[j].z;
        float p2 = cs[j].y  + cs[j].z + cs[j].w;
        float p3 = cs[j].z  + cs[j].w + right;
        const int base = (x0 + j) * WVAL + c0;
        // ascending index + strict '>' preserves first-occurrence semantics
        if (p0 > best) { best = p0; bidx = base;     }
        if (p1 > best) { best = p1; bidx = base + 1; }
        if (p2 > best) { best = p2; bidx = base + 2; }
        if (p3 > best) { best = p3; bidx = base + 3; }
    }

    // ---- Phase 4: warp shfl reduce, then ONE smem atomicMax per warp ----
    #pragma unroll
    for (int off = 16; off > 0; off >>= 1) {
        float v2 = __shfl_down_sync(0xffffffffu, best, off);
        int   i2 = __shfl_down_sync(0xffffffffu, bidx, off);
        if (v2 > best || (v2 == best && i2 < bidx)) { best = v2; bidx = i2; }
    }
    __syncthreads();                         // s_best init visible
    if (lane == 0) {
        const unsigned long long packed =
            ((unsigned long long)float_to_ordered(best) << 32) |
            (unsigned long long)(~(unsigned int)bidx);
        atomicMax(&s_best, packed);
    }
    __syncthreads();                         // all 16 contributions in

    // ---- Phase 5: warp 0: gather + loss + counter; last CTA does the mean ----
    if (warp == 0) {
        unsigned cnt = 0;
        if (lane == 0) {
            const int idx = (int)(~(unsigned int)(s_best & 0xFFFFFFFFull));
            const float* __restrict__ pk = pred + (size_t)bk * CVAL * HW;
            const float* __restrict__ g  = gt   + (size_t)bk * CVAL;
            float loss = 0.0f;
            #pragma unroll
            for (int c = 0; c < CVAL; ++c) {
                float d = pk[c * HW + idx] - g[c];
                loss = fmaf(d, d, loss);
            }
            g_labelloss_scratch[bk] = loss;
            __threadfence();                              // scratch before count
            cnt = atomicAdd(&g_labelloss_count, 1u);
        }
        cnt = __shfl_sync(0xffffffffu, cnt, 0);

        if (cnt == NBK - 1) {                             // last CTA: final mean
            __threadfence();                              // acquire all scratch
            if (lane < BVAL) {
                float s = 0.0f;
                #pragma unroll
                for (int k = 0; k < KVAL; ++k)            // fixed order, MLP=11
                    s += g_labelloss_scratch[lane * KVAL + k];
                out[lane] = s * (1.0f / (float)KVAL);
            }
            if (lane == 0) g_labelloss_count = 0;         // reset for next replay
        }
    }
}

extern "C" void kernel_launch(void* const* d_in, const int* in_sizes, int n_in,
                              void* d_out, int out_size)
{
    const float* pred    = (const float*)d_in[0];
    const float* gt      = (const float*)d_in[1];
    const float* heatmap = (const float*)d_in[2];
    float* out = (float*)d_out;

    labelloss_fused_kernel<<<NBK, NTHREADS>>>(pred, gt, heatmap, out);
}